// round 1
// baseline (speedup 1.0000x reference)
#include <cuda_runtime.h>
#include <math.h>

// Problem constants
#define Nn   2048
#define CIN  2
#define Hh   32
#define EMB  16
#define HOR  12
#define Bb   32
#define Tt   16
#define RW   1088   // width of R/G: 64 (x part, b*2+c) + 1024 (h part, b*32+k)

// Device scratch (no allocations allowed)
__device__ float g_A[Nn * Nn];      // adjacency, 16 MB
__device__ float g_R[Nn * RW];      // RHS: [n][ x(64) | h(1024) ]
__device__ float g_G[Nn * RW];      // G = A @ R
__device__ float g_C[Nn * Bb * Hh]; // cell state [n][b][h]

// ---------------------------------------------------------------------------
// A = softmax(relu(E1 @ E2^T), axis=-1) ; one block per row
// ---------------------------------------------------------------------------
__global__ __launch_bounds__(256) void adj_kernel(const float* __restrict__ E1,
                                                  const float* __restrict__ E2) {
    int r = blockIdx.x;
    int tid = threadIdx.x;
    __shared__ float e1[EMB];
    __shared__ float red[256];
    if (tid < EMB) e1[tid] = E1[r * EMB + tid];
    __syncthreads();

    float v[8];
    float mx = -1e30f;
#pragma unroll
    for (int i = 0; i < 8; i++) {
        int c = tid + i * 256;
        float d = 0.f;
#pragma unroll
        for (int e = 0; e < EMB; e++) d += e1[e] * E2[c * EMB + e];
        d = fmaxf(d, 0.f);
        v[i] = d;
        mx = fmaxf(mx, d);
    }
    red[tid] = mx; __syncthreads();
    for (int s = 128; s > 0; s >>= 1) {
        if (tid < s) red[tid] = fmaxf(red[tid], red[tid + s]);
        __syncthreads();
    }
    mx = red[0]; __syncthreads();

    float sum = 0.f;
#pragma unroll
    for (int i = 0; i < 8; i++) { v[i] = expf(v[i] - mx); sum += v[i]; }
    red[tid] = sum; __syncthreads();
    for (int s = 128; s > 0; s >>= 1) {
        if (tid < s) red[tid] += red[tid + s];
        __syncthreads();
    }
    float inv = 1.0f / red[0];
#pragma unroll
    for (int i = 0; i < 8; i++) g_A[r * Nn + tid + i * 256] = v[i] * inv;
}

// ---------------------------------------------------------------------------
// Copy x[:, t, :, :] into R[:, 0:64]   (R[n][b*2+c] = x[b][t][n][c])
// ---------------------------------------------------------------------------
__global__ __launch_bounds__(256) void copyx_kernel(const float* __restrict__ x, int t) {
    int idx = blockIdx.x * 256 + threadIdx.x;       // b*N*C + n*C + c  (read-coalesced)
    int c = idx & 1;
    int n = (idx >> 1) & (Nn - 1);
    int b = idx >> 12;
    g_R[n * RW + b * 2 + c] = x[(((size_t)b * Tt + t) * Nn + n) * CIN + c];
}

// ---------------------------------------------------------------------------
// SGEMM: G[2048 x 1088] = A[2048 x 2048] @ R[2048 x 1088]
// 128x64 block tile, BK=16, 256 threads, 8x4 per thread, reg-staged loads
// ---------------------------------------------------------------------------
#define LDA_S 132
__global__ __launch_bounds__(256) void sgemm_kernel(const float* __restrict__ A,
                                                    const float* __restrict__ Bm,
                                                    float* __restrict__ Cm) {
    __shared__ float As[16 * LDA_S];
    __shared__ float Bs[16 * 64];
    int tid = threadIdx.x;
    int m0 = blockIdx.y * 128;
    int n0 = blockIdx.x * 64;
    int tx = tid & 15;      // 16 -> 64 cols (4 each)
    int ty = tid >> 4;      // 16 -> 128 rows (8 each)

    int aRow = tid >> 2;          // 0..63
    int aCol = (tid & 3) * 4;     // 0,4,8,12
    int bRow = tid >> 4;          // 0..15
    int bCol = (tid & 15) * 4;    // 0..60

    const float* Aptr = A + (size_t)(m0 + aRow) * Nn + aCol;
    const float* Bptr = Bm + (size_t)bRow * RW + n0 + bCol;

    float acc[8][4];
#pragma unroll
    for (int i = 0; i < 8; i++)
#pragma unroll
        for (int j = 0; j < 4; j++) acc[i][j] = 0.f;

    float4 ra0 = *(const float4*)(Aptr);
    float4 ra1 = *(const float4*)(Aptr + (size_t)64 * Nn);
    float4 rb  = *(const float4*)(Bptr);

    for (int k0 = 0; k0 < Nn; k0 += 16) {
        __syncthreads();
        {
            const float* pa0 = (const float*)&ra0;
            const float* pa1 = (const float*)&ra1;
#pragma unroll
            for (int i = 0; i < 4; i++) {
                As[(aCol + i) * LDA_S + aRow]      = pa0[i];
                As[(aCol + i) * LDA_S + 64 + aRow] = pa1[i];
            }
            *(float4*)&Bs[bRow * 64 + bCol] = rb;
        }
        __syncthreads();

        if (k0 + 16 < Nn) {
            Aptr += 16;
            Bptr += (size_t)16 * RW;
            ra0 = *(const float4*)(Aptr);
            ra1 = *(const float4*)(Aptr + (size_t)64 * Nn);
            rb  = *(const float4*)(Bptr);
        }

#pragma unroll
        for (int kk = 0; kk < 16; kk++) {
            float4 av0 = *(const float4*)&As[kk * LDA_S + ty * 8];
            float4 av1 = *(const float4*)&As[kk * LDA_S + ty * 8 + 4];
            float4 bv  = *(const float4*)&Bs[kk * 64 + tx * 4];
            const float* av = (const float*)&av0;
            const float* aw = (const float*)&av1;
            const float* bp = (const float*)&bv;
#pragma unroll
            for (int i = 0; i < 4; i++)
#pragma unroll
                for (int j = 0; j < 4; j++) {
                    acc[i][j]     += av[i] * bp[j];
                    acc[i + 4][j] += aw[i] * bp[j];
                }
        }
    }

#pragma unroll
    for (int i = 0; i < 8; i++) {
        float4 o = make_float4(acc[i][0], acc[i][1], acc[i][2], acc[i][3]);
        *(float4*)&Cm[(size_t)(m0 + ty * 8 + i) * RW + n0 + tx * 4] = o;
    }
}

// ---------------------------------------------------------------------------
// LSTM gates + state update.
// Row p = n*32 + b; warp handles 8 consecutive rows; lane = hidden unit.
// gates = AX@Wx + AH@Wh + (bx+bh); i,f,o = sigmoid; g = tanh
// c' = f*c + i*g ; h' = o*tanh(c') written back into R[:, 64:]
// ---------------------------------------------------------------------------
__global__ __launch_bounds__(256) void lstm_kernel(const float* __restrict__ Wx,
                                                   const float* __restrict__ bx,
                                                   const float* __restrict__ Wh,
                                                   const float* __restrict__ bh) {
    __shared__ float Whs[32 * 128];
    __shared__ float Wxs[2 * 128];
    __shared__ float bs[128];
    int tid = threadIdx.x;
    for (int i = tid; i < 32 * 128; i += 256) Whs[i] = Wh[i];
    if (tid < 256) Wxs[tid] = Wx[tid];
    if (tid < 128) bs[tid] = bx[tid] + bh[tid];
    __syncthreads();

    int warp = tid >> 5, lane = tid & 31;
    int row0 = (blockIdx.x * 8 + warp) * 8;

    for (int rr = 0; rr < 8; rr++) {
        int p = row0 + rr;
        int n = p >> 5;
        int b = p & 31;
        const float* Grow = g_G + (size_t)n * RW;
        float ax0 = Grow[b * 2];
        float ax1 = Grow[b * 2 + 1];
        float ahv = Grow[64 + b * 32 + lane];

        float ai = bs[lane]      + ax0 * Wxs[lane]       + ax1 * Wxs[128 + lane];
        float af = bs[32 + lane] + ax0 * Wxs[32 + lane]  + ax1 * Wxs[128 + 32 + lane];
        float ao = bs[64 + lane] + ax0 * Wxs[64 + lane]  + ax1 * Wxs[128 + 64 + lane];
        float ag = bs[96 + lane] + ax0 * Wxs[96 + lane]  + ax1 * Wxs[128 + 96 + lane];

#pragma unroll
        for (int k = 0; k < 32; k++) {
            float a = __shfl_sync(0xffffffffu, ahv, k);
            ai += a * Whs[k * 128 + lane];
            af += a * Whs[k * 128 + 32 + lane];
            ao += a * Whs[k * 128 + 64 + lane];
            ag += a * Whs[k * 128 + 96 + lane];
        }

        float iv = 1.0f / (1.0f + expf(-ai));
        float fv = 1.0f / (1.0f + expf(-af));
        float ov = 1.0f / (1.0f + expf(-ao));
        float gv = tanhf(ag);

        size_t cidx = (size_t)n * (Bb * Hh) + b * 32 + lane;
        float c = g_C[cidx];
        float cn = fv * c + iv * gv;
        g_C[cidx] = cn;
        g_R[(size_t)n * RW + 64 + b * 32 + lane] = ov * tanhf(cn);
    }
}

// ---------------------------------------------------------------------------
// out[b, hz, n, 0] = sum_k h[b,n,k] * Wp[k,hz] + bp[hz]
// ---------------------------------------------------------------------------
__global__ __launch_bounds__(256) void proj_kernel(const float* __restrict__ Wp,
                                                   const float* __restrict__ bp,
                                                   float* __restrict__ out) {
    int idx = blockIdx.x * 256 + threadIdx.x;  // b*2048 + n
    int n = idx & (Nn - 1);
    int b = idx >> 11;
    const float* h = g_R + (size_t)n * RW + 64 + b * 32;
    float hv[32];
#pragma unroll
    for (int k = 0; k < 32; k++) hv[k] = h[k];
#pragma unroll
    for (int hz = 0; hz < HOR; hz++) {
        float s = bp[hz];
#pragma unroll
        for (int k = 0; k < 32; k++) s += hv[k] * Wp[k * HOR + hz];
        out[((size_t)b * HOR + hz) * Nn + n] = s;
    }
}

// ---------------------------------------------------------------------------
extern "C" void kernel_launch(void* const* d_in, const int* in_sizes, int n_in,
                              void* d_out, int out_size) {
    const float* x  = (const float*)d_in[0];
    const float* E1 = (const float*)d_in[1];
    const float* E2 = (const float*)d_in[2];
    const float* Wx = (const float*)d_in[3];
    const float* bx = (const float*)d_in[4];
    const float* Wh = (const float*)d_in[5];
    const float* bh = (const float*)d_in[6];
    const float* Wp = (const float*)d_in[7];
    const float* bp = (const float*)d_in[8];
    float* out = (float*)d_out;

    void *pR, *pC, *pA, *pG;
    cudaGetSymbolAddress(&pR, g_R);
    cudaGetSymbolAddress(&pC, g_C);
    cudaGetSymbolAddress(&pA, g_A);
    cudaGetSymbolAddress(&pG, g_G);

    // zero h part of R and cell state (deterministic start)
    cudaMemsetAsync(pR, 0, sizeof(float) * Nn * RW, 0);
    cudaMemsetAsync(pC, 0, sizeof(float) * Nn * Bb * Hh, 0);

    adj_kernel<<<Nn, 256>>>(E1, E2);

    dim3 gemmGrid(RW / 64, Nn / 128);  // (17, 16)
    for (int t = 0; t < Tt; t++) {
        copyx_kernel<<<(Bb * Nn * CIN) / 256, 256>>>(x, t);
        sgemm_kernel<<<gemmGrid, 256>>>((const float*)pA, (const float*)pR, (float*)pG);
        lstm_kernel<<<(Nn * Bb) / 64, 256>>>(Wx, bx, Wh, bh);
    }

    proj_kernel<<<(Bb * Nn) / 256, 256>>>(Wp, bp, out);
}

// round 2
// speedup vs baseline: 2.0406x; 2.0406x over previous
#include <cuda_runtime.h>
#include <math.h>
#include <stdint.h>

// Problem constants
#define Nn   2048
#define CIN  2
#define Hh   32
#define EMB  16
#define HOR  12
#define Bb   32
#define Tt   16
#define GW   1152   // padded width of G / rows of R_T: 64 x-part + 1024 h-part + 64 pad
#define KD   2048

// Device scratch
__device__ float g_A [Nn * Nn];       // adjacency row-major (temp)
__device__ float g_At[Nn * Nn];       // adjacency transposed [k][m]
__device__ float g_RT[GW * KD];       // R^T: [col][node]
__device__ float g_G [Nn * GW];       // G = A @ R : [node][col]
__device__ float g_C [Nn * Bb * Hh];  // cell state

// ---------------------------------------------------------------------------
__device__ __forceinline__ float to_tf32(float x) {
    uint32_t u;
    asm("cvt.rna.tf32.f32 %0, %1;" : "=r"(u) : "f"(x));
    return __uint_as_float(u);
}
__device__ __forceinline__ float fsig(float x) { return 1.0f / (1.0f + __expf(-x)); }
__device__ __forceinline__ float ftanh(float x) { return 2.0f / (1.0f + __expf(-2.0f * x)) - 1.0f; }

__device__ __forceinline__ void cp16(float* dst, const float* src) {
    uint32_t s = (uint32_t)__cvta_generic_to_shared(dst);
    asm volatile("cp.async.cg.shared.global [%0], [%1], 16;" :: "r"(s), "l"(src));
}

__device__ __forceinline__ void mma_tf32(float (&d)[4], const uint32_t (&a)[4], const uint32_t (&b)[2]) {
    asm volatile(
        "mma.sync.aligned.m16n8k8.row.col.f32.tf32.tf32.f32 "
        "{%0,%1,%2,%3}, {%4,%5,%6,%7}, {%8,%9}, {%0,%1,%2,%3};"
        : "+f"(d[0]), "+f"(d[1]), "+f"(d[2]), "+f"(d[3])
        : "r"(a[0]), "r"(a[1]), "r"(a[2]), "r"(a[3]), "r"(b[0]), "r"(b[1]));
}

// ---------------------------------------------------------------------------
// A = softmax(relu(E1 @ E2^T)) row-major, values tf32-rounded
// ---------------------------------------------------------------------------
__global__ __launch_bounds__(256) void adj_kernel(const float* __restrict__ E1,
                                                  const float* __restrict__ E2) {
    int r = blockIdx.x;
    int tid = threadIdx.x;
    __shared__ float e1[EMB];
    __shared__ float red[256];
    if (tid < EMB) e1[tid] = E1[r * EMB + tid];
    __syncthreads();

    float v[8];
    float mx = -1e30f;
#pragma unroll
    for (int i = 0; i < 8; i++) {
        int c = tid + i * 256;
        float d = 0.f;
#pragma unroll
        for (int e = 0; e < EMB; e++) d += e1[e] * E2[c * EMB + e];
        d = fmaxf(d, 0.f);
        v[i] = d;
        mx = fmaxf(mx, d);
    }
    red[tid] = mx; __syncthreads();
    for (int s = 128; s > 0; s >>= 1) {
        if (tid < s) red[tid] = fmaxf(red[tid], red[tid + s]);
        __syncthreads();
    }
    mx = red[0]; __syncthreads();

    float sum = 0.f;
#pragma unroll
    for (int i = 0; i < 8; i++) { v[i] = expf(v[i] - mx); sum += v[i]; }
    red[tid] = sum; __syncthreads();
    for (int s = 128; s > 0; s >>= 1) {
        if (tid < s) red[tid] += red[tid + s];
        __syncthreads();
    }
    float inv = 1.0f / red[0];
#pragma unroll
    for (int i = 0; i < 8; i++) g_A[(size_t)r * Nn + tid + i * 256] = to_tf32(v[i] * inv);
}

// 32x32 tiled transpose: g_At[k][m] = g_A[m][k]
__global__ __launch_bounds__(256) void transpose_kernel() {
    __shared__ float t[32][33];
    int x = blockIdx.x * 32 + threadIdx.x;
    int y = blockIdx.y * 32 + threadIdx.y;
#pragma unroll
    for (int j = 0; j < 4; j++)
        t[threadIdx.y + 8 * j][threadIdx.x] = g_A[(size_t)(y + 8 * j) * Nn + x];
    __syncthreads();
    int x2 = blockIdx.y * 32 + threadIdx.x;
    int y2 = blockIdx.x * 32 + threadIdx.y;
#pragma unroll
    for (int j = 0; j < 4; j++)
        g_At[(size_t)(y2 + 8 * j) * Nn + x2] = t[threadIdx.x][threadIdx.y + 8 * j];
}

// ---------------------------------------------------------------------------
// R_T[b*2+c][node] = tf32(x[b][t][node][c])
// ---------------------------------------------------------------------------
__global__ __launch_bounds__(256) void copyx_kernel(const float* __restrict__ x, int t) {
    int idx = blockIdx.x * 256 + threadIdx.x;  // col*2048 + node
    int node = idx & (Nn - 1);
    int col = idx >> 11;        // 0..63
    int b = col >> 1;
    int c = col & 1;
    g_RT[(size_t)col * KD + node] =
        to_tf32(x[(((size_t)b * Tt + t) * Nn + node) * CIN + c]);
}

// ---------------------------------------------------------------------------
// Tensor-core SGEMM (tf32): G[2048 x 1152] = A[2048 x 2048] @ R_T^T
//   At: [k][m] row-major (transposed A), Bt = R_T: [n][k] row-major
// 128x128 block tile, BK=32, 128 threads (4 warps of 64x64), 3-stage cp.async
// ---------------------------------------------------------------------------
#define ASZ (32 * 136)
#define BSZ (128 * 36)
#define SSTAGE (ASZ + BSZ)

__global__ void __launch_bounds__(128, 1)
sgemm_tc(const float* __restrict__ At, const float* __restrict__ Bt, float* __restrict__ C) {
    extern __shared__ float smem[];
    int tid = threadIdx.x;
    int lane = tid & 31;
    int w = tid >> 5;
    int bm0 = blockIdx.y * 128;
    int bn0 = blockIdx.x * 128;
    int wm0 = (w & 1) * 64;
    int wn0 = (w >> 1) * 64;

    float acc[4][8][4];
#pragma unroll
    for (int mt = 0; mt < 4; mt++)
#pragma unroll
        for (int nt = 0; nt < 8; nt++)
#pragma unroll
            for (int i = 0; i < 4; i++) acc[mt][nt][i] = 0.f;

    // ---- stage loader ----
    auto load_stage = [&](int s, int k0) {
        float* sA = smem + s * SSTAGE;
        float* sB = sA + ASZ;
#pragma unroll
        for (int i = 0; i < 8; i++) {
            int ch = tid + i * 128;
            int r = ch >> 5;
            int c = (ch & 31) * 4;
            cp16(sA + r * 136 + c, At + (size_t)(k0 + r) * Nn + bm0 + c);
        }
#pragma unroll
        for (int i = 0; i < 8; i++) {
            int ch = tid + i * 128;
            int n = ch >> 3;
            int c = (ch & 7) * 4;
            cp16(sB + n * 36 + c, Bt + (size_t)(bn0 + n) * KD + k0 + c);
        }
    };

    load_stage(0, 0);
    asm volatile("cp.async.commit_group;" ::: "memory");
    load_stage(1, 32);
    asm volatile("cp.async.commit_group;" ::: "memory");

    const int NIT = KD / 32;  // 64
    for (int it = 0; it < NIT; ++it) {
        if (it + 2 < NIT) {
            asm volatile("cp.async.wait_group 1;" ::: "memory");
        } else {
            asm volatile("cp.async.wait_group 0;" ::: "memory");
        }
        __syncthreads();
        if (it + 2 < NIT) {
            load_stage((it + 2) % 3, (it + 2) * 32);
            asm volatile("cp.async.commit_group;" ::: "memory");
        }

        const float* sA = smem + (it % 3) * SSTAGE;
        const float* sB = sA + ASZ;
#pragma unroll
        for (int kk = 0; kk < 4; kk++) {
            uint32_t af[4][4];
#pragma unroll
            for (int mt = 0; mt < 4; mt++) {
                const float* pa = sA + (kk * 8 + (lane & 3)) * 136 + wm0 + mt * 16 + (lane >> 2);
                af[mt][0] = __float_as_uint(pa[0]);
                af[mt][1] = __float_as_uint(pa[8]);
                af[mt][2] = __float_as_uint(pa[4 * 136]);
                af[mt][3] = __float_as_uint(pa[4 * 136 + 8]);
            }
            uint32_t bf[8][2];
#pragma unroll
            for (int nt = 0; nt < 8; nt++) {
                const float* pb = sB + (wn0 + nt * 8 + (lane >> 2)) * 36 + kk * 8 + (lane & 3);
                bf[nt][0] = __float_as_uint(pb[0]);
                bf[nt][1] = __float_as_uint(pb[4]);
            }
#pragma unroll
            for (int mt = 0; mt < 4; mt++)
#pragma unroll
                for (int nt = 0; nt < 8; nt++) mma_tf32(acc[mt][nt], af[mt], bf[nt]);
        }
    }

    // epilogue
#pragma unroll
    for (int mt = 0; mt < 4; mt++) {
        int r0 = bm0 + wm0 + mt * 16 + (lane >> 2);
#pragma unroll
        for (int nt = 0; nt < 8; nt++) {
            int c0 = bn0 + wn0 + nt * 8 + 2 * (lane & 3);
            *(float2*)&C[(size_t)r0 * GW + c0] = make_float2(acc[mt][nt][0], acc[mt][nt][1]);
            *(float2*)&C[(size_t)(r0 + 8) * GW + c0] = make_float2(acc[mt][nt][2], acc[mt][nt][3]);
        }
    }
}

// ---------------------------------------------------------------------------
// LSTM gates + state update. Warp handles 8 rows (2 groups of 4).
// Whs4[k][lane] = {Wh[k][lane], Wh[k][32+lane], Wh[k][64+lane], Wh[k][96+lane]}
// ---------------------------------------------------------------------------
__global__ __launch_bounds__(256) void lstm_kernel(const float* __restrict__ Wx,
                                                   const float* __restrict__ bx,
                                                   const float* __restrict__ Wh,
                                                   const float* __restrict__ bh) {
    __shared__ float4 Whs4[32 * 32];
    __shared__ float4 Wxs4[2 * 32];
    __shared__ float4 bs4[32];
    int tid = threadIdx.x;
    for (int i = tid; i < 1024; i += 256) {
        int k = i >> 5, l = i & 31;
        Whs4[i] = make_float4(Wh[k * 128 + l], Wh[k * 128 + 32 + l],
                              Wh[k * 128 + 64 + l], Wh[k * 128 + 96 + l]);
    }
    if (tid < 64) {
        int c = tid >> 5, l = tid & 31;
        Wxs4[tid] = make_float4(Wx[c * 128 + l], Wx[c * 128 + 32 + l],
                                Wx[c * 128 + 64 + l], Wx[c * 128 + 96 + l]);
    }
    if (tid < 32) {
        bs4[tid] = make_float4(bx[tid] + bh[tid], bx[32 + tid] + bh[32 + tid],
                               bx[64 + tid] + bh[64 + tid], bx[96 + tid] + bh[96 + tid]);
    }
    __syncthreads();

    int warp = tid >> 5, lane = tid & 31;
    int p0 = (blockIdx.x * 8 + warp) * 8;

#pragma unroll
    for (int grp = 0; grp < 2; grp++) {
        float4 acc[4];
        float ahv[4];
        int pn[4], pb[4];
#pragma unroll
        for (int r = 0; r < 4; r++) {
            int p = p0 + grp * 4 + r;
            int n = p >> 5;
            int b = p & 31;
            pn[r] = n; pb[r] = b;
            const float* Gr = g_G + (size_t)n * GW;
            float ax0 = Gr[b * 2];
            float ax1 = Gr[b * 2 + 1];
            ahv[r] = Gr[64 + b * 32 + lane];
            float4 a = bs4[lane];
            float4 w0 = Wxs4[lane];
            float4 w1 = Wxs4[32 + lane];
            a.x += ax0 * w0.x + ax1 * w1.x;
            a.y += ax0 * w0.y + ax1 * w1.y;
            a.z += ax0 * w0.z + ax1 * w1.z;
            a.w += ax0 * w0.w + ax1 * w1.w;
            acc[r] = a;
        }
#pragma unroll
        for (int k = 0; k < 32; k++) {
            float4 w = Whs4[k * 32 + lane];
#pragma unroll
            for (int r = 0; r < 4; r++) {
                float a = __shfl_sync(0xffffffffu, ahv[r], k);
                acc[r].x += a * w.x;
                acc[r].y += a * w.y;
                acc[r].z += a * w.z;
                acc[r].w += a * w.w;
            }
        }
#pragma unroll
        for (int r = 0; r < 4; r++) {
            float iv = fsig(acc[r].x);
            float fv = fsig(acc[r].y);
            float ov = fsig(acc[r].z);
            float gv = ftanh(acc[r].w);
            size_t cidx = (size_t)pn[r] * (Bb * Hh) + pb[r] * 32 + lane;
            float c = g_C[cidx];
            float cn = fv * c + iv * gv;
            g_C[cidx] = cn;
            float h = ov * ftanh(cn);
            g_RT[(size_t)(64 + pb[r] * 32 + lane) * KD + pn[r]] = to_tf32(h);
        }
    }
}

// ---------------------------------------------------------------------------
// out[b, hz, n, 0] = sum_k h[b,n,k] * Wp[k,hz] + bp[hz]
// ---------------------------------------------------------------------------
__global__ __launch_bounds__(256) void proj_kernel(const float* __restrict__ Wp,
                                                   const float* __restrict__ bp,
                                                   float* __restrict__ out) {
    int idx = blockIdx.x * 256 + threadIdx.x;  // b*2048 + n
    int n = idx & (Nn - 1);
    int b = idx >> 11;
    float hv[32];
#pragma unroll
    for (int k = 0; k < 32; k++) hv[k] = g_RT[(size_t)(64 + b * 32 + k) * KD + n];
#pragma unroll
    for (int hz = 0; hz < HOR; hz++) {
        float s = bp[hz];
#pragma unroll
        for (int k = 0; k < 32; k++) s += hv[k] * Wp[k * HOR + hz];
        out[((size_t)b * HOR + hz) * Nn + n] = s;
    }
}

// ---------------------------------------------------------------------------
extern "C" void kernel_launch(void* const* d_in, const int* in_sizes, int n_in,
                              void* d_out, int out_size) {
    const float* x  = (const float*)d_in[0];
    const float* E1 = (const float*)d_in[1];
    const float* E2 = (const float*)d_in[2];
    const float* Wx = (const float*)d_in[3];
    const float* bx = (const float*)d_in[4];
    const float* Wh = (const float*)d_in[5];
    const float* bh = (const float*)d_in[6];
    const float* Wp = (const float*)d_in[7];
    const float* bp = (const float*)d_in[8];
    float* out = (float*)d_out;

    void *pRT, *pC, *pAt, *pG;
    cudaGetSymbolAddress(&pRT, g_RT);
    cudaGetSymbolAddress(&pC, g_C);
    cudaGetSymbolAddress(&pAt, g_At);
    cudaGetSymbolAddress(&pG, g_G);

    static int smem_set = 0;
    if (!smem_set) {
        cudaFuncSetAttribute(sgemm_tc, cudaFuncAttributeMaxDynamicSharedMemorySize,
                             3 * SSTAGE * (int)sizeof(float));
        smem_set = 1;
    }

    cudaMemsetAsync(pRT, 0, sizeof(float) * GW * KD, 0);
    cudaMemsetAsync(pC, 0, sizeof(float) * Nn * Bb * Hh, 0);

    adj_kernel<<<Nn, 256>>>(E1, E2);
    transpose_kernel<<<dim3(64, 64), dim3(32, 8)>>>();

    dim3 gemmGrid(GW / 128, Nn / 128);  // (9, 16)
    size_t gemmSmem = 3 * SSTAGE * sizeof(float);
    for (int t = 0; t < Tt; t++) {
        copyx_kernel<<<(64 * Nn) / 256, 256>>>(x, t);
        sgemm_tc<<<gemmGrid, 128, gemmSmem>>>((const float*)pAt, (const float*)pRT, (float*)pG);
        lstm_kernel<<<(Nn * Bb) / 64, 256>>>(Wx, bx, Wh, bh);
    }

    proj_kernel<<<(Bb * Nn) / 256, 256>>>(Wp, bp, out);
}